// round 2
// baseline (speedup 1.0000x reference)
#include <cuda_runtime.h>
#include <cuda_bf16.h>

#define Bn 16
#define Sn 512
#define Tn 16
#define Pn 4
#define Gn 128                 // Sn / Pn
#define NPATCH (Bn * Gn * Gn)  // 262144

// Intermediate normalized CAM, layout [b, gy, gx, t] (t contiguous) — 16 MB scratch.
__device__ float g_top[(size_t)NPATCH * Tn];

// ---------------------------------------------------------------------------
// Kernel 1: per-patch c[t] = sum_k input[b, gy*4+py, gx*4+px, t] * W[n, k, 0]
// then (c - min_t) / (max_t - min_t). 16 threads per patch (one per t).
// ---------------------------------------------------------------------------
__global__ void __launch_bounds__(256)
patch_cam_kernel(const float* __restrict__ input, const float* __restrict__ w3)
{
    int tid = blockIdx.x * blockDim.x + threadIdx.x;
    int t = tid & 15;
    int n = tid >> 4;                 // patch index: ((b*G)+gy)*G + gx
    int gx = n & (Gn - 1);
    int gy = (n >> 7) & (Gn - 1);
    int b  = n >> 14;

    // Thread t loads W[n, k=t, m=0] (stride 6 floats); broadcast via shfl below.
    float w = __ldg(&w3[n * (Pn * Pn * 6) + t * 6]);

    const float* base = input + (((size_t)b * Sn + gy * Pn) * Sn + gx * Pn) * Tn + t;

    int lane = threadIdx.x & 31;
    unsigned grp = (unsigned)(lane & 16);   // which 16-lane half of the warp

    float acc = 0.0f;
    #pragma unroll
    for (int k = 0; k < 16; ++k) {
        float wk = __shfl_sync(0xffffffffu, w, (int)(grp | (unsigned)k));
        int py = k >> 2;
        int px = k & 3;
        acc = fmaf(base[((size_t)py * Sn + px) * Tn], wk, acc);
    }

    // min / max over the 16 t-lanes of this patch (xor 8,4,2,1 stays in-group)
    float mn = acc, mx = acc;
    #pragma unroll
    for (int o = 8; o >= 1; o >>= 1) {
        mn = fminf(mn, __shfl_xor_sync(0xffffffffu, mn, o));
        mx = fmaxf(mx, __shfl_xor_sync(0xffffffffu, mx, o));
    }

    g_top[(size_t)n * Tn + t] = (acc - mn) / (mx - mn);
}

// ---------------------------------------------------------------------------
// Kernel 2: bilinear upsample (g,g) -> (s,s), align_corners=True.
// Each thread computes 4 consecutive x outputs for one (b, y).
// Over an x-strip of 4, j0 spans at most 2 values -> only 3 columns x 2 rows
// of patch vectors are needed: 24 LDG.128 for 4 outputs (6/output vs 16).
// ---------------------------------------------------------------------------
__device__ __forceinline__ float4 sel4(int s, const float4& a, const float4& b)
{
    return s ? b : a;
}

__global__ void __launch_bounds__(128)
upsample_kernel(float* __restrict__ out)
{
    int idx = blockIdx.x * blockDim.x + threadIdx.x;   // (b, y, xg)
    int xg = idx & (Gn - 1);          // x-strip index, 128 strips of 4
    int y  = (idx >> 7) & (Sn - 1);
    int b  = idx >> 16;

    const float r = 127.0f / 511.0f;  // (Gn-1)/(Sn-1)

    float cy = (float)y * r;
    int i0 = min((int)cy, Gn - 2);
    float wy = cy - (float)i0;

    int x0 = xg << 2;
    int jb = min((int)((float)x0 * r), Gn - 2);
    int d2 = (jb + 2 <= Gn - 1) ? 2 : 1;   // clamp third column at grid edge

    const float4* r0 = (const float4*)&g_top[(((size_t)b * Gn + i0) * Gn + jb) * Tn];
    const float4* r1 = (const float4*)&g_top[(((size_t)b * Gn + i0 + 1) * Gn + jb) * Tn];

    // Preload 3 columns x 2 rows of 16-float patch vectors (24 float4).
    float4 a0[4], a1[4], a2[4];   // row i0,   cols jb, jb+1, jb+2
    float4 c0[4], c1[4], c2[4];   // row i0+1, cols jb, jb+1, jb+2
    #pragma unroll
    for (int q = 0; q < 4; ++q) {
        a0[q] = r0[q];
        a1[q] = r0[4 + q];
        a2[q] = r0[d2 * 4 + q];
        c0[q] = r1[q];
        c1[q] = r1[4 + q];
        c2[q] = r1[d2 * 4 + q];
    }

    float4* o = (float4*)(out + (((size_t)(b * Sn + y)) * Sn + x0) * Tn);

    #pragma unroll
    for (int u = 0; u < 4; ++u) {
        int x = x0 + u;
        float cx = (float)x * r;
        int j0 = min((int)cx, Gn - 2);
        float wx = cx - (float)j0;
        int s = j0 - jb;              // 0 or 1

        float w00 = (1.0f - wy) * (1.0f - wx);
        float w01 = (1.0f - wy) * wx;
        float w10 = wy * (1.0f - wx);
        float w11 = wy * wx;

        #pragma unroll
        for (int q = 0; q < 4; ++q) {
            float4 A = sel4(s, a0[q], a1[q]);   // row i0,   col j0
            float4 C = sel4(s, a1[q], a2[q]);   // row i0,   col j0+1
            float4 D = sel4(s, c0[q], c1[q]);   // row i0+1, col j0
            float4 E = sel4(s, c1[q], c2[q]);   // row i0+1, col j0+1
            float4 v;
            v.x = w00 * A.x + w01 * C.x + w10 * D.x + w11 * E.x;
            v.y = w00 * A.y + w01 * C.y + w10 * D.y + w11 * E.y;
            v.z = w00 * A.z + w01 * C.z + w10 * D.z + w11 * E.z;
            v.w = w00 * A.w + w01 * C.w + w10 * D.w + w11 * E.w;
            o[u * 4 + q] = v;
        }
    }
}

extern "C" void kernel_launch(void* const* d_in, const int* in_sizes, int n_in,
                              void* d_out, int out_size)
{
    const float* input = (const float*)d_in[0];   // (16,512,512,16) f32
    const float* w3    = (const float*)d_in[1];   // (262144,16,6)  f32
    float* out = (float*)d_out;                   // (16*512*512, 16) f32

    // Kernel 1: NPATCH * 16 threads
    {
        int total = NPATCH * Tn;                  // 4,194,304
        patch_cam_kernel<<<total / 256, 256>>>(input, w3);
    }
    // Kernel 2: B * S * (S/4) threads, 4 x-outputs each
    {
        int total = Bn * Sn * Gn;                 // 1,048,576
        upsample_kernel<<<total / 128, 128>>>(out);
    }
    (void)in_sizes; (void)n_in; (void)out_size;
}

// round 3
// speedup vs baseline: 1.2162x; 1.2162x over previous
#include <cuda_runtime.h>
#include <cuda_bf16.h>

#define Bn 16
#define Sn 512
#define Tn 16
#define Pn 4
#define Gn 128                 // Sn / Pn
#define NPATCH (Bn * Gn * Gn)  // 262144

// Intermediate normalized CAM, layout [b, gy, gx, t] (t contiguous) — 16 MB scratch.
__device__ float g_top[(size_t)NPATCH * Tn];

// ---------------------------------------------------------------------------
// Kernel 1: per-patch c[t] = sum_k input[b, gy*4+py, gx*4+px, t] * W[n, k, 0]
// then (c - min_t) / (max_t - min_t). 16 threads per patch (one per t).
// ---------------------------------------------------------------------------
__global__ void __launch_bounds__(256)
patch_cam_kernel(const float* __restrict__ input, const float* __restrict__ w3)
{
    int tid = blockIdx.x * blockDim.x + threadIdx.x;
    int t = tid & 15;
    int n = tid >> 4;                 // patch index: ((b*G)+gy)*G + gx
    int gx = n & (Gn - 1);
    int gy = (n >> 7) & (Gn - 1);
    int b  = n >> 14;

    // Thread t loads W[n, k=t, m=0] (stride 6 floats); broadcast via shfl below.
    float w = __ldg(&w3[n * (Pn * Pn * 6) + t * 6]);

    const float* base = input + (((size_t)b * Sn + gy * Pn) * Sn + gx * Pn) * Tn + t;

    int lane = threadIdx.x & 31;
    unsigned grp = (unsigned)(lane & 16);   // which 16-lane half of the warp

    float acc = 0.0f;
    #pragma unroll
    for (int k = 0; k < 16; ++k) {
        float wk = __shfl_sync(0xffffffffu, w, (int)(grp | (unsigned)k));
        int py = k >> 2;
        int px = k & 3;
        acc = fmaf(base[((size_t)py * Sn + px) * Tn], wk, acc);
    }

    // min / max over the 16 t-lanes of this patch (xor 8,4,2,1 stays in-group)
    float mn = acc, mx = acc;
    #pragma unroll
    for (int o = 8; o >= 1; o >>= 1) {
        mn = fminf(mn, __shfl_xor_sync(0xffffffffu, mn, o));
        mx = fmaxf(mx, __shfl_xor_sync(0xffffffffu, mx, o));
    }

    g_top[(size_t)n * Tn + t] = (acc - mn) / (mx - mn);
}

// ---------------------------------------------------------------------------
// Kernel 2: bilinear upsample (g,g)->(s,s), align_corners=True, via smem.
// Block = (b, 4 output rows) x full width 512. The 4 rows need <=3 g_top rows;
// load them to smem padded to 20 floats/col (conflict-free float4 reads).
// Thread (ylocal = tid>>6, xs = tid&63) computes x = xs + 64*u, u=0..7.
// ---------------------------------------------------------------------------
#define COLPAD 20   // floats per padded column (80 B, 16B-aligned)

__global__ void __launch_bounds__(256)
upsample_kernel(float* __restrict__ out)
{
    __shared__ float s[3 * Gn * COLPAD];     // 30720 B

    int blk = blockIdx.x;
    int yt = blk & (Gn - 1);                 // y-tile (4 rows each)
    int b  = blk >> 7;
    int y0 = yt << 2;

    const float r = 127.0f / 511.0f;

    int ia = min((int)((float)y0 * r), Gn - 2);

    // Cooperative load: 3 rows x 512 float4 -> padded smem
    for (int i = threadIdx.x; i < 3 * 512; i += 256) {
        int row = i >> 9;                    // 0..2
        int j   = i & 511;                   // float4 index within row
        int gr  = min(ia + row, Gn - 1);
        float4 v = ((const float4*)&g_top[((size_t)(b * Gn + gr)) * (Gn * Tn)])[j];
        int col = j >> 2, q = j & 3;
        *(float4*)&s[(row * Gn + col) * COLPAD + q * 4] = v;
    }
    __syncthreads();

    int ylocal = threadIdx.x >> 6;
    int xs     = threadIdx.x & 63;
    int y = y0 + ylocal;

    float cy = (float)y * r;
    int i0 = min((int)cy, Gn - 2);
    float wy = cy - (float)i0;
    int r0 = i0 - ia;                        // 0 or 1

    const float* srow0 = &s[(r0)     * Gn * COLPAD];
    const float* srow1 = &s[(r0 + 1) * Gn * COLPAD];

    #pragma unroll
    for (int u = 0; u < 8; ++u) {
        int x = xs + (u << 6);
        float cx = (float)x * r;
        int j0 = min((int)cx, Gn - 2);
        float wx = cx - (float)j0;

        float w00 = (1.0f - wy) * (1.0f - wx);
        float w01 = (1.0f - wy) * wx;
        float w10 = wy * (1.0f - wx);
        float w11 = wy * wx;

        const float4* A = (const float4*)&srow0[j0 * COLPAD];
        const float4* Bp = A + (COLPAD / 4);     // col j0+1
        const float4* C = (const float4*)&srow1[j0 * COLPAD];
        const float4* D = C + (COLPAD / 4);

        float4* o = (float4*)(out + (((size_t)(b * Sn + y)) * Sn + x) * Tn);
        #pragma unroll
        for (int q = 0; q < 4; ++q) {
            float4 a = A[q], bb = Bp[q], c = C[q], d = D[q];
            float4 v;
            v.x = w00 * a.x + w01 * bb.x + w10 * c.x + w11 * d.x;
            v.y = w00 * a.y + w01 * bb.y + w10 * c.y + w11 * d.y;
            v.z = w00 * a.z + w01 * bb.z + w10 * c.z + w11 * d.z;
            v.w = w00 * a.w + w01 * bb.w + w10 * c.w + w11 * d.w;
            o[q] = v;
        }
    }
}

extern "C" void kernel_launch(void* const* d_in, const int* in_sizes, int n_in,
                              void* d_out, int out_size)
{
    const float* input = (const float*)d_in[0];   // (16,512,512,16) f32
    const float* w3    = (const float*)d_in[1];   // (262144,16,6)  f32
    float* out = (float*)d_out;                   // (16*512*512, 16) f32

    // Kernel 1: NPATCH * 16 threads
    {
        int total = NPATCH * Tn;                  // 4,194,304
        patch_cam_kernel<<<total / 256, 256>>>(input, w3);
    }
    // Kernel 2: 16 b x 128 y-tiles
    {
        upsample_kernel<<<Bn * Gn, 256>>>(out);
    }
    (void)in_sizes; (void)n_in; (void)out_size;
}

// round 4
// speedup vs baseline: 1.3175x; 1.0833x over previous
#include <cuda_runtime.h>
#include <cuda_bf16.h>

#define Bn 16
#define Sn 512
#define Tn 16
#define Pn 4
#define Gn 128                 // Sn / Pn
#define NPATCH (Bn * Gn * Gn)  // 262144

// Intermediate normalized CAM, layout [b, gy, gx, t] (t contiguous) — 16 MB scratch.
__device__ float g_top[(size_t)NPATCH * Tn];

// ---------------------------------------------------------------------------
// Kernel 1: per-patch c[t] = sum_k input[b, gy*4+py, gx*4+px, t] * W[n, k, 0]
// then (c - min_t) / (max_t - min_t). 16 threads per patch (one per t).
// ---------------------------------------------------------------------------
__global__ void __launch_bounds__(256)
patch_cam_kernel(const float* __restrict__ input, const float* __restrict__ w3)
{
    int tid = blockIdx.x * blockDim.x + threadIdx.x;
    int t = tid & 15;
    int n = tid >> 4;                 // patch index: ((b*G)+gy)*G + gx
    int gx = n & (Gn - 1);
    int gy = (n >> 7) & (Gn - 1);
    int b  = n >> 14;

    // Thread t loads W[n, k=t, m=0] (stride 6 floats); broadcast via shfl below.
    float w = __ldg(&w3[n * (Pn * Pn * 6) + t * 6]);

    const float* base = input + (((size_t)b * Sn + gy * Pn) * Sn + gx * Pn) * Tn + t;

    int lane = threadIdx.x & 31;
    unsigned grp = (unsigned)(lane & 16);   // which 16-lane half of the warp

    float acc = 0.0f;
    #pragma unroll
    for (int k = 0; k < 16; ++k) {
        float wk = __shfl_sync(0xffffffffu, w, (int)(grp | (unsigned)k));
        int py = k >> 2;
        int px = k & 3;
        acc = fmaf(base[((size_t)py * Sn + px) * Tn], wk, acc);
    }

    // min / max over the 16 t-lanes of this patch (xor 8,4,2,1 stays in-group)
    float mn = acc, mx = acc;
    #pragma unroll
    for (int o = 8; o >= 1; o >>= 1) {
        mn = fminf(mn, __shfl_xor_sync(0xffffffffu, mn, o));
        mx = fmaxf(mx, __shfl_xor_sync(0xffffffffu, mx, o));
    }

    g_top[(size_t)n * Tn + t] = (acc - mn) / (mx - mn);
}

// ---------------------------------------------------------------------------
// Kernel 2: bilinear upsample (g,g)->(s,s), align_corners=True.
// Block = (b, 4 output rows) x full width 512.
// Stage 1: y-pre-blend the needed g_top rows into smem yb[4][128][16]
//          (padded to 20 floats/col). Reads come straight from L2.
// Stage 2: per pixel only x-blend: 8 LDS.128 + 4 STG.128.
// ---------------------------------------------------------------------------
#define COLPAD 20   // floats per padded column (80 B, 16B-aligned)

__global__ void __launch_bounds__(256)
upsample_kernel(float* __restrict__ out)
{
    __shared__ float s[4 * Gn * COLPAD];     // 40960 B: y-blended rows

    int blk = blockIdx.x;
    int yt = blk & (Gn - 1);                 // y-tile (4 rows each)
    int b  = blk >> 7;
    int y0 = yt << 2;

    const float r = 127.0f / 511.0f;

    // Stage 1: 4 rows x 128 cols x 4 float4 = 2048 items, 8 per thread.
    #pragma unroll
    for (int it = 0; it < 8; ++it) {
        int i = threadIdx.x + (it << 8);
        int row = i >> 9;                    // 0..3 local y
        int rem = i & 511;
        int col = rem >> 2;
        int q   = rem & 3;

        int y = y0 + row;
        float cy = (float)y * r;
        int i0 = min((int)cy, Gn - 2);
        float wy = cy - (float)i0;

        const float4* g0 = (const float4*)&g_top[(((size_t)(b * Gn + i0))     * Gn + col) * Tn];
        const float4* g1 = (const float4*)&g_top[(((size_t)(b * Gn + i0 + 1)) * Gn + col) * Tn];
        float4 a = g0[q], c = g1[q];
        float4 v;
        v.x = a.x + wy * (c.x - a.x);
        v.y = a.y + wy * (c.y - a.y);
        v.z = a.z + wy * (c.z - a.z);
        v.w = a.w + wy * (c.w - a.w);
        *(float4*)&s[(row * Gn + col) * COLPAD + q * 4] = v;
    }
    __syncthreads();

    // Stage 2: thread (ylocal = tid>>6, xs = tid&63) does x = xs + 64*u.
    int ylocal = threadIdx.x >> 6;
    int xs     = threadIdx.x & 63;
    int y = y0 + ylocal;
    const float* srow = &s[ylocal * Gn * COLPAD];

    #pragma unroll
    for (int u = 0; u < 8; ++u) {
        int x = xs + (u << 6);
        float cx = (float)x * r;
        int j0 = min((int)cx, Gn - 2);
        float wx = cx - (float)j0;

        const float4* A = (const float4*)&srow[j0 * COLPAD];
        const float4* Bp = A + (COLPAD / 4);     // col j0+1

        float4* o = (float4*)(out + (((size_t)(b * Sn + y)) * Sn + x) * Tn);
        #pragma unroll
        for (int q = 0; q < 4; ++q) {
            float4 a = A[q], bb = Bp[q];
            float4 v;
            v.x = a.x + wx * (bb.x - a.x);
            v.y = a.y + wx * (bb.y - a.y);
            v.z = a.z + wx * (bb.z - a.z);
            v.w = a.w + wx * (bb.w - a.w);
            o[q] = v;
        }
    }
}

extern "C" void kernel_launch(void* const* d_in, const int* in_sizes, int n_in,
                              void* d_out, int out_size)
{
    const float* input = (const float*)d_in[0];   // (16,512,512,16) f32
    const float* w3    = (const float*)d_in[1];   // (262144,16,6)  f32
    float* out = (float*)d_out;                   // (16*512*512, 16) f32

    // Kernel 1: NPATCH * 16 threads
    {
        int total = NPATCH * Tn;                  // 4,194,304
        patch_cam_kernel<<<total / 256, 256>>>(input, w3);
    }
    // Kernel 2: 16 b x 128 y-tiles
    {
        upsample_kernel<<<Bn * Gn, 256>>>(out);
    }
    (void)in_sizes; (void)n_in; (void)out_size;
}